// round 13
// baseline (speedup 1.0000x reference)
#include <cuda_runtime.h>
#include <cuda_fp16.h>
#include <math.h>
#include <stdint.h>

// Problem constants
#define Bb 4
#define Ss 2048
#define Dd 1024
#define Hh 4096
#define MM (Bb * Ss)   // 8192

// ---------------------------------------------------------------------------
// Device-global scratch (allocation-free rule). fp16 (rn-rounded) operands.
// ---------------------------------------------------------------------------
__device__ __half g_xh[(size_t)MM * Dd];
__device__ __half g_w1h[(size_t)Hh * Dd];
__device__ __half g_w2h[(size_t)Dd * Hh];
__device__ __half g_hh[(size_t)MM * Hh];   // post-GELU hidden, fp16
__device__ float g_U1[MM * 4];
__device__ float g_V[MM * 16];

__device__ __forceinline__ float gelu_exact(float v) {
    return 0.5f * v * (1.0f + erff(v * 0.70710678118654752f));
}

__device__ __forceinline__ uint32_t smem_u32(const void* p) {
    uint32_t a;
    asm("{ .reg .u64 t; cvta.to.shared.u64 t, %1; cvt.u32.u64 %0, t; }"
        : "=r"(a) : "l"(p));
    return a;
}

// ---------------------------------------------------------------------------
// fp16 mma / ldmatrix / cp.async primitives
// ---------------------------------------------------------------------------
__device__ __forceinline__ void mma16816h(float* d, const uint32_t* a, const uint32_t* b) {
    asm volatile(
        "mma.sync.aligned.m16n8k16.row.col.f32.f16.f16.f32 "
        "{%0,%1,%2,%3}, {%4,%5,%6,%7}, {%8,%9}, {%0,%1,%2,%3};"
        : "+f"(d[0]), "+f"(d[1]), "+f"(d[2]), "+f"(d[3])
        : "r"(a[0]), "r"(a[1]), "r"(a[2]), "r"(a[3]), "r"(b[0]), "r"(b[1]));
}

__device__ __forceinline__ void ldm4(uint32_t* r, uint32_t addr) {
    asm volatile("ldmatrix.sync.aligned.m8n8.x4.shared.b16 {%0,%1,%2,%3}, [%4];"
                 : "=r"(r[0]), "=r"(r[1]), "=r"(r[2]), "=r"(r[3]) : "r"(addr));
}

__device__ __forceinline__ void cp16(uint32_t s, const void* g) {
    asm volatile("cp.async.cg.shared.global [%0], [%1], 16;" :: "r"(s), "l"(g));
}
__device__ __forceinline__ void cp_commit() {
    asm volatile("cp.async.commit_group;" ::: "memory");
}
template <int N>
__device__ __forceinline__ void cp_wait() {
    asm volatile("cp.async.wait_group %0;" :: "n"(N) : "memory");
}

// ---------------------------------------------------------------------------
// Tiling: 256x128 CTA tile (BM=256, BN=128), BK=64 fp16, 3-stage ring, occ 1.
// Warp grid 4(M) x 2(N): warp tile 64x64 -> A mult 2x, B mult 4x.
// ---------------------------------------------------------------------------
#define BK 64
#define TSTRIDE 144                   // 64 fp16 = 128 B data + 16 B pad
#define TILE_A (256 * TSTRIDE)        // 36864 B
#define TILE_Bt (128 * TSTRIDE)       // 18432 B
#define STAGE_B (TILE_A + TILE_Bt)    // 55296 B per stage
#define NSTAGE 3
#define SMEM_TOTAL (NSTAGE * STAGE_B) // 165888 B

extern __shared__ char dsmem[];

// Issue cp.async for one BK=64 chunk: A(256 rows) + B(128 rows), 12 cp16/thread.
__device__ __forceinline__ void issue_chunk(
    uint32_t sbuf, const __half* __restrict__ Ah, const __half* __restrict__ Bh,
    int m0, int n0, int kc, int KDIM, int tid)
{
    #pragma unroll
    for (int i = 0; i < 12; i++) {
        int idx = tid + i * 256;          // 0..3071
        if (idx < 2048) {                 // A: 256 rows x 8 chunks
            int row = idx >> 3, c = idx & 7;
            uint32_t soff = (uint32_t)(row * TSTRIDE + c * 16);
            size_t ga = (size_t)(m0 + row) * KDIM + kc * BK + c * 8;
            cp16(sbuf + soff, Ah + ga);
        } else {                          // B: 128 rows x 8 chunks
            int j = idx - 2048;
            int row = j >> 3, c = j & 7;
            uint32_t soff = (uint32_t)(row * TSTRIDE + c * 16);
            size_t gb = (size_t)(n0 + row) * KDIM + kc * BK + c * 8;
            cp16(sbuf + TILE_A + soff, Bh + gb);
        }
    }
}

// Load 4 A fragments (64 rows x k16).
__device__ __forceinline__ void lda(uint32_t a[4][4], uint32_t tile, int wm, int lane, int ks) {
    uint32_t koff = (uint32_t)(ks * 32 + (lane >> 4) * 16);
    #pragma unroll
    for (int mi = 0; mi < 4; mi++) {
        uint32_t addr = tile + (uint32_t)((wm * 64 + mi * 16 + (lane & 15)) * TSTRIDE) + koff;
        ldm4(a[mi], addr);
    }
}

// Load 8 B fragments (64 cols x k16) via 4 ldmatrix.x4.
__device__ __forceinline__ void ldb(uint32_t b[8][2], uint32_t tile, int wn, int lane, int ks) {
    #pragma unroll
    for (int g = 0; g < 4; g++) {
        int nrow = wn * 64 + g * 16 + (lane & 7) + ((lane >> 4) & 1) * 8;
        uint32_t addr = tile + (uint32_t)(nrow * TSTRIDE) +
                        (uint32_t)(ks * 32 + ((lane >> 3) & 1) * 16);
        uint32_t r[4];
        ldm4(r, addr);
        b[2 * g][0] = r[0]; b[2 * g][1] = r[1];
        b[2 * g + 1][0] = r[2]; b[2 * g + 1][1] = r[3];
    }
}

// One BK=64 chunk: 4 k16-steps, each 8 LDSM + 32 MMA.
__device__ __forceinline__ void compute_chunk(uint32_t sbuf, int wm, int wn, int lane,
                                              float acc[4][8][4]) {
    #pragma unroll
    for (int ks = 0; ks < 4; ks++) {
        uint32_t a[4][4], b[8][2];
        lda(a, sbuf, wm, lane, ks);
        ldb(b, sbuf + TILE_A, wn, lane, ks);
        #pragma unroll
        for (int mi = 0; mi < 4; mi++)
            #pragma unroll
            for (int ni = 0; ni < 8; ni++)
                mma16816h(acc[mi][ni], a[mi], b[ni]);
    }
}

// Mainloop: 3-stage ring, 2-deep prefetch, correctness-safe 2 syncs per chunk.
template <int KDIM>
__device__ __forceinline__ void gemm_f16(
    const __half* __restrict__ Ah, const __half* __restrict__ Bh,
    int m0, int n0, float acc[4][8][4])
{
    int tid = threadIdx.x;
    int lane = tid & 31, wid = tid >> 5;
    int wm = wid >> 1, wn = wid & 1;
    uint32_t sbase = smem_u32(dsmem);

    #pragma unroll
    for (int mi = 0; mi < 4; mi++)
        #pragma unroll
        for (int ni = 0; ni < 8; ni++)
            #pragma unroll
            for (int q = 0; q < 4; q++) acc[mi][ni][q] = 0.f;

    const int NC = KDIM / BK;
    issue_chunk(sbase + 0 * STAGE_B, Ah, Bh, m0, n0, 0, KDIM, tid);
    cp_commit();
    issue_chunk(sbase + 1 * STAGE_B, Ah, Bh, m0, n0, 1, KDIM, tid);
    cp_commit();

    int st_c = 0;                         // stage of chunk c
    for (int c = 0; c < NC; c++) {
        __syncthreads();                  // overwrite guard: compute(c-1) done everywhere
        if (c + 2 < NC) {
            int st_n = st_c + 2; if (st_n >= NSTAGE) st_n -= NSTAGE;
            issue_chunk(sbase + st_n * STAGE_B, Ah, Bh, m0, n0, c + 2, KDIM, tid);
            cp_commit();
            cp_wait<2>();                 // outstanding c,c+1,c+2 -> c retired
        } else if (c + 1 < NC) {
            cp_wait<1>();                 // outstanding c,c+1 -> c retired
        } else {
            cp_wait<0>();
        }
        __syncthreads();                  // publish all threads' arrivals
        compute_chunk(sbase + st_c * STAGE_B, wm, wn, lane, acc);
        if (++st_c == NSTAGE) st_c = 0;
    }
}

// ---------------------------------------------------------------------------
// cvt: fp32 -> fp16 (round-to-nearest)
// ---------------------------------------------------------------------------
__global__ void cvt_f16_kernel(const float* __restrict__ src,
                               __half* __restrict__ dst, int n4) {
    int i = blockIdx.x * blockDim.x + threadIdx.x;
    if (i >= n4) return;
    float4 v = ((const float4*)src)[i];
    __half2* d = (__half2*)dst;
    d[2 * i]     = __floats2half2_rn(v.x, v.y);
    d[2 * i + 1] = __floats2half2_rn(v.z, v.w);
}

// ---------------------------------------------------------------------------
// U1[b,s,r] = x[b,s,:] . x[b, 2+2r, :]  (fp32 exact); 1 warp/(b,s)
// ---------------------------------------------------------------------------
__global__ void u1_kernel(const float* __restrict__ x) {
    int gw = (blockIdx.x * blockDim.x + threadIdx.x) >> 5;
    int lane = threadIdx.x & 31;
    if (gw >= MM) return;
    int b = gw >> 11;
    const float4* xr = (const float4*)(x + (size_t)gw * Dd);
    const float4* o0 = (const float4*)(x + ((size_t)b * Ss + 2) * Dd);
    const float4* o1 = (const float4*)(x + ((size_t)b * Ss + 4) * Dd);
    const float4* o2 = (const float4*)(x + ((size_t)b * Ss + 6) * Dd);
    const float4* o3 = (const float4*)(x + ((size_t)b * Ss + 8) * Dd);
    float a0 = 0.f, a1 = 0.f, a2 = 0.f, a3 = 0.f;
    for (int j = lane; j < Dd / 4; j += 32) {
        float4 xv = xr[j];
        float4 v;
        v = o0[j]; a0 += xv.x * v.x + xv.y * v.y + xv.z * v.z + xv.w * v.w;
        v = o1[j]; a1 += xv.x * v.x + xv.y * v.y + xv.z * v.z + xv.w * v.w;
        v = o2[j]; a2 += xv.x * v.x + xv.y * v.y + xv.z * v.z + xv.w * v.w;
        v = o3[j]; a3 += xv.x * v.x + xv.y * v.y + xv.z * v.z + xv.w * v.w;
    }
    #pragma unroll
    for (int off = 16; off; off >>= 1) {
        a0 += __shfl_xor_sync(0xFFFFFFFFu, a0, off);
        a1 += __shfl_xor_sync(0xFFFFFFFFu, a1, off);
        a2 += __shfl_xor_sync(0xFFFFFFFFu, a2, off);
        a3 += __shfl_xor_sync(0xFFFFFFFFu, a3, off);
    }
    if (lane == 0) {
        g_U1[gw * 4 + 0] = a0;
        g_U1[gw * 4 + 1] = a1;
        g_U1[gw * 4 + 2] = a2;
        g_U1[gw * 4 + 3] = a3;
    }
}

// ---------------------------------------------------------------------------
// V[b,s,r,k] = sum_j h[b,s,k*1024+j] * x[b,10+2r,j]; h from g_hh (fp16)
// ---------------------------------------------------------------------------
__global__ void v_kernel(const float* __restrict__ x) {
    int gw = (blockIdx.x * blockDim.x + threadIdx.x) >> 5;
    int lane = threadIdx.x & 31;
    if (gw >= MM) return;
    int b = gw >> 11;
    const float2* od[4];
    #pragma unroll
    for (int r = 0; r < 4; r++)
        od[r] = (const float2*)(x + ((size_t)b * Ss + 10 + 2 * r) * Dd);
    float acc[16];
    #pragma unroll
    for (int i = 0; i < 16; i++) acc[i] = 0.f;
    #pragma unroll
    for (int k = 0; k < 4; k++) {
        const __half2* hh = (const __half2*)(g_hh + (size_t)gw * Hh + k * 1024);
        for (int j = lane; j < 512; j += 32) {
            float2 hv = __half22float2(hh[j]);
            #pragma unroll
            for (int r = 0; r < 4; r++) {
                float2 ov = od[r][j];
                acc[r * 4 + k] += hv.x * ov.x + hv.y * ov.y;
            }
        }
    }
    #pragma unroll
    for (int i = 0; i < 16; i++) {
        #pragma unroll
        for (int off = 16; off; off >>= 1)
            acc[i] += __shfl_xor_sync(0xFFFFFFFFu, acc[i], off);
    }
    if (lane == 0) {
        #pragma unroll
        for (int i = 0; i < 16; i++) g_V[gw * 16 + i] = acc[i];
    }
}

// ---------------------------------------------------------------------------
// GEMM1: h = gelu(x@W1^T + scale*lora1 + b1) -> fp16 g_hh
// ---------------------------------------------------------------------------
__global__ __launch_bounds__(256, 1)
void gemm1_mma(const float* __restrict__ x, const float* __restrict__ b1,
               const float* __restrict__ scale_p) {
    int m0 = blockIdx.y * 256, n0 = blockIdx.x * 128;
    float acc[4][8][4];
    gemm_f16<Dd>(g_xh, g_w1h, m0, n0, acc);

    int lane = threadIdx.x & 31, wid = threadIdx.x >> 5;
    int wm = wid >> 1, wn = wid & 1;
    float sc = *scale_p;
    int r = n0 >> 10;
    #pragma unroll
    for (int mi = 0; mi < 4; mi++) {
        #pragma unroll
        for (int half = 0; half < 2; half++) {
            int m = m0 + wm * 64 + mi * 16 + (lane >> 2) + half * 8;
            int b = m >> 11;
            float u = sc * g_U1[m * 4 + r];
            const float* ev = x + ((size_t)b * Ss + 1 + 2 * r) * Dd;
            #pragma unroll
            for (int ni = 0; ni < 8; ni++) {
                int n = n0 + wn * 64 + ni * 8 + 2 * (lane & 3);
                int nc = n & 1023;
                float c0 = acc[mi][ni][half * 2 + 0] + u * ev[nc]     + b1[n];
                float c1 = acc[mi][ni][half * 2 + 1] + u * ev[nc + 1] + b1[n + 1];
                *(__half2*)(g_hh + (size_t)m * Hh + n) =
                    __floats2half2_rn(gelu_exact(c0), gelu_exact(c1));
            }
        }
    }
}

// ---------------------------------------------------------------------------
// GEMM2: out = h@W2^T + scale*lora2 + b2  (fp32 out)
// ---------------------------------------------------------------------------
__global__ __launch_bounds__(256, 1)
void gemm2_mma(const float* __restrict__ x, const float* __restrict__ b2,
               const float* __restrict__ scale_p, float* __restrict__ out) {
    int m0 = blockIdx.y * 256, n0 = blockIdx.x * 128;
    float acc[4][8][4];
    gemm_f16<Hh>(g_hh, g_w2h, m0, n0, acc);

    int lane = threadIdx.x & 31, wid = threadIdx.x >> 5;
    int wm = wid >> 1, wn = wid & 1;
    float sc = *scale_p;
    int r = n0 >> 8;
    #pragma unroll
    for (int mi = 0; mi < 4; mi++) {
        #pragma unroll
        for (int half = 0; half < 2; half++) {
            int m = m0 + wm * 64 + mi * 16 + (lane >> 2) + half * 8;
            int b = m >> 11;
            float4 vv = *(const float4*)&g_V[m * 16 + r * 4];
            const float4* ev2 = (const float4*)(x + ((size_t)b * Ss + 9 + 2 * r) * Dd);
            #pragma unroll
            for (int ni = 0; ni < 8; ni++) {
                int n = n0 + wn * 64 + ni * 8 + 2 * (lane & 3);
                float4 e0 = ev2[n & 255];
                float4 e1 = ev2[(n + 1) & 255];
                float lora0 = vv.x * e0.x + vv.y * e0.y + vv.z * e0.z + vv.w * e0.w;
                float lora1 = vv.x * e1.x + vv.y * e1.y + vv.z * e1.z + vv.w * e1.w;
                float2 o;
                o.x = acc[mi][ni][half * 2 + 0] + sc * lora0 + b2[n];
                o.y = acc[mi][ni][half * 2 + 1] + sc * lora1 + b2[n + 1];
                *(float2*)(out + (size_t)m * Dd + n) = o;
            }
        }
    }
}

// ---------------------------------------------------------------------------
extern "C" void kernel_launch(void* const* d_in, const int* in_sizes, int n_in,
                              void* d_out, int out_size) {
    const float* x     = (const float*)d_in[0];
    const float* W1    = (const float*)d_in[1];
    const float* b1    = (const float*)d_in[2];
    const float* W2    = (const float*)d_in[3];
    const float* b2    = (const float*)d_in[4];
    const float* scale = (const float*)d_in[5];
    float* out = (float*)d_out;

    cudaFuncSetAttribute(gemm1_mma, cudaFuncAttributeMaxDynamicSharedMemorySize, SMEM_TOTAL);
    cudaFuncSetAttribute(gemm2_mma, cudaFuncAttributeMaxDynamicSharedMemorySize, SMEM_TOTAL);

    __half *xh, *w1h, *w2h;
    cudaGetSymbolAddress((void**)&xh, g_xh);
    cudaGetSymbolAddress((void**)&w1h, g_w1h);
    cudaGetSymbolAddress((void**)&w2h, g_w2h);

    u1_kernel<<<MM / 8, 256>>>(x);

    cvt_f16_kernel<<<(MM * Dd / 4 + 255) / 256, 256>>>(x, xh, MM * Dd / 4);
    cvt_f16_kernel<<<(Hh * Dd / 4 + 255) / 256, 256>>>(W1, w1h, Hh * Dd / 4);
    cvt_f16_kernel<<<(Dd * Hh / 4 + 255) / 256, 256>>>(W2, w2h, Dd * Hh / 4);

    dim3 g1(Hh / 128, MM / 256);   // (32, 32) = 1024 CTAs
    gemm1_mma<<<g1, 256, SMEM_TOTAL>>>(x, b1, scale);

    v_kernel<<<MM / 8, 256>>>(x);

    dim3 g2(Dd / 128, MM / 256);   // (8, 32) = 256 CTAs
    gemm2_mma<<<g2, 256, SMEM_TOTAL>>>(x, b2, scale, out);
}

// round 14
// speedup vs baseline: 1.1302x; 1.1302x over previous
#include <cuda_runtime.h>
#include <cuda_fp16.h>
#include <math.h>
#include <stdint.h>

// Problem constants
#define Bb 4
#define Ss 2048
#define Dd 1024
#define Hh 4096
#define MM (Bb * Ss)   // 8192

// ---------------------------------------------------------------------------
// Device-global scratch (allocation-free rule). fp16 (rn-rounded) operands.
// ---------------------------------------------------------------------------
__device__ __half g_xh[(size_t)MM * Dd];
__device__ __half g_w1h[(size_t)Hh * Dd];
__device__ __half g_w2h[(size_t)Dd * Hh];
__device__ __half g_hh[(size_t)MM * Hh];   // post-GELU hidden, fp16
__device__ float g_U1[MM * 4];
__device__ float g_V[MM * 16];

__device__ __forceinline__ float gelu_exact(float v) {
    return 0.5f * v * (1.0f + erff(v * 0.70710678118654752f));
}

__device__ __forceinline__ uint32_t smem_u32(const void* p) {
    uint32_t a;
    asm("{ .reg .u64 t; cvta.to.shared.u64 t, %1; cvt.u32.u64 %0, t; }"
        : "=r"(a) : "l"(p));
    return a;
}

// ---------------------------------------------------------------------------
// fp16 mma / ldmatrix / cp.async primitives
// ---------------------------------------------------------------------------
__device__ __forceinline__ void mma16816h(float* d, const uint32_t* a, const uint32_t* b) {
    asm volatile(
        "mma.sync.aligned.m16n8k16.row.col.f32.f16.f16.f32 "
        "{%0,%1,%2,%3}, {%4,%5,%6,%7}, {%8,%9}, {%0,%1,%2,%3};"
        : "+f"(d[0]), "+f"(d[1]), "+f"(d[2]), "+f"(d[3])
        : "r"(a[0]), "r"(a[1]), "r"(a[2]), "r"(a[3]), "r"(b[0]), "r"(b[1]));
}

__device__ __forceinline__ void ldm4(uint32_t* r, uint32_t addr) {
    asm volatile("ldmatrix.sync.aligned.m8n8.x4.shared.b16 {%0,%1,%2,%3}, [%4];"
                 : "=r"(r[0]), "=r"(r[1]), "=r"(r[2]), "=r"(r[3]) : "r"(addr));
}

__device__ __forceinline__ void cp16(uint32_t s, const void* g) {
    asm volatile("cp.async.cg.shared.global [%0], [%1], 16;" :: "r"(s), "l"(g));
}
__device__ __forceinline__ void cp_commit() {
    asm volatile("cp.async.commit_group;" ::: "memory");
}
template <int N>
__device__ __forceinline__ void cp_wait() {
    asm volatile("cp.async.wait_group %0;" :: "n"(N) : "memory");
}

// ---------------------------------------------------------------------------
// Tiling: 128x128 CTA tile, BK=64 fp16, 3-stage ring, ONE sync per chunk,
// 2 CTAs/SM (110.6 KB smem per CTA; 2x fits in 228 KB).
// ---------------------------------------------------------------------------
#define BK 64
#define TSTRIDE 144                   // 64 fp16 = 128 B data + 16 B pad
#define TILE_B (128 * TSTRIDE)        // 18432 B per tile
#define STAGE_B (2 * TILE_B)          // A + B = 36864 B per stage
#define NSTAGE 3
#define SMEM_TOTAL (NSTAGE * STAGE_B) // 110592 B

extern __shared__ char dsmem[];

// Issue cp.async for one BK=64 chunk: 8 cp16 per thread (A + B tiles).
__device__ __forceinline__ void issue_chunk(
    uint32_t sbuf, const __half* __restrict__ Ah, const __half* __restrict__ Bh,
    int m0, int n0, int kc, int KDIM, int tid)
{
    #pragma unroll
    for (int i = 0; i < 4; i++) {
        int idx = tid + i * 256;          // 0..1023
        int row = idx >> 3, c = idx & 7;  // 128 rows x 8 16B-chunks
        uint32_t soff = (uint32_t)(row * TSTRIDE + c * 16);
        size_t ga = (size_t)(m0 + row) * KDIM + kc * BK + c * 8;
        size_t gb = (size_t)(n0 + row) * KDIM + kc * BK + c * 8;
        cp16(sbuf + soff, Ah + ga);
        cp16(sbuf + TILE_B + soff, Bh + gb);
    }
}

// Load 4 A fragments (64 rows x k16) from a tile.
__device__ __forceinline__ void lda(uint32_t a[4][4], uint32_t tile, int wm, int lane, int ks) {
    uint32_t koff = (uint32_t)(ks * 32 + (lane >> 4) * 16);
    #pragma unroll
    for (int mi = 0; mi < 4; mi++) {
        uint32_t addr = tile + (uint32_t)((wm * 64 + mi * 16 + (lane & 15)) * TSTRIDE) + koff;
        ldm4(a[mi], addr);
    }
}

// Load 4 B fragments (32 cols x k16) from a tile.
__device__ __forceinline__ void ldb(uint32_t b[4][2], uint32_t tile, int wn, int lane, int ks) {
    #pragma unroll
    for (int g = 0; g < 2; g++) {
        int nrow = wn * 32 + g * 16 + (lane & 7) + ((lane >> 4) & 1) * 8;
        uint32_t addr = tile + (uint32_t)(nrow * TSTRIDE) +
                        (uint32_t)(ks * 32 + ((lane >> 3) & 1) * 16);
        uint32_t r[4];
        ldm4(r, addr);
        b[2 * g][0] = r[0]; b[2 * g][1] = r[1];
        b[2 * g + 1][0] = r[2]; b[2 * g + 1][1] = r[3];
    }
}

// One BK=64 chunk, single-term fp16: 4 k16-steps, each 6 LDSM + 16 MMA.
__device__ __forceinline__ void compute_chunk(uint32_t sbuf, int wm, int wn, int lane,
                                              float acc[4][4][4]) {
    #pragma unroll
    for (int ks = 0; ks < 4; ks++) {
        uint32_t a[4][4], b[4][2];
        lda(a, sbuf, wm, lane, ks);
        ldb(b, sbuf + TILE_B, wn, lane, ks);
        #pragma unroll
        for (int mi = 0; mi < 4; mi++)
            #pragma unroll
            for (int ni = 0; ni < 4; ni++)
                mma16816h(acc[mi][ni], a[mi], b[ni]);
    }
}

// Mainloop: 3-stage ring, prefetch depth 2, ONE merged sync per chunk.
// Safety: the sync after cp_wait (a) publishes stage-c arrivals to all warps,
// (b) certifies every warp finished compute(c-1); issue(c+2) then overwrites
// stage (c+2)%3 == (c-1)%3, which is exactly the stage guarded by (b).
template <int KDIM>
__device__ __forceinline__ void gemm_f16(
    const __half* __restrict__ Ah, const __half* __restrict__ Bh,
    int m0, int n0, float acc[4][4][4])
{
    int tid = threadIdx.x;
    int lane = tid & 31, wid = tid >> 5;
    int wm = wid >> 2, wn = wid & 3;
    uint32_t sbase = smem_u32(dsmem);

    #pragma unroll
    for (int mi = 0; mi < 4; mi++)
        #pragma unroll
        for (int ni = 0; ni < 4; ni++)
            #pragma unroll
            for (int q = 0; q < 4; q++) acc[mi][ni][q] = 0.f;

    const int NC = KDIM / BK;
    issue_chunk(sbase + 0 * STAGE_B, Ah, Bh, m0, n0, 0, KDIM, tid);
    cp_commit();
    issue_chunk(sbase + 1 * STAGE_B, Ah, Bh, m0, n0, 1, KDIM, tid);
    cp_commit();

    int st_c = 0;
    for (int c = 0; c < NC; c++) {
        if (c + 1 < NC) cp_wait<1>();     // outstanding {c, c+1} -> c retired
        else            cp_wait<0>();
        __syncthreads();                  // publish arrivals + guard stage (c-1)
        if (c + 2 < NC) {
            int st_n = st_c + 2; if (st_n >= NSTAGE) st_n -= NSTAGE;
            issue_chunk(sbase + st_n * STAGE_B, Ah, Bh, m0, n0, c + 2, KDIM, tid);
            cp_commit();
        }
        compute_chunk(sbase + st_c * STAGE_B, wm, wn, lane, acc);
        if (++st_c == NSTAGE) st_c = 0;
    }
}

// ---------------------------------------------------------------------------
// cvt: fp32 -> fp16 (round-to-nearest)
// ---------------------------------------------------------------------------
__global__ void cvt_f16_kernel(const float* __restrict__ src,
                               __half* __restrict__ dst, int n4) {
    int i = blockIdx.x * blockDim.x + threadIdx.x;
    if (i >= n4) return;
    float4 v = ((const float4*)src)[i];
    __half2* d = (__half2*)dst;
    d[2 * i]     = __floats2half2_rn(v.x, v.y);
    d[2 * i + 1] = __floats2half2_rn(v.z, v.w);
}

// ---------------------------------------------------------------------------
// U1[b,s,r] = x[b,s,:] . x[b, 2+2r, :]  (fp32 exact); 1 warp/(b,s)
// ---------------------------------------------------------------------------
__global__ void u1_kernel(const float* __restrict__ x) {
    int gw = (blockIdx.x * blockDim.x + threadIdx.x) >> 5;
    int lane = threadIdx.x & 31;
    if (gw >= MM) return;
    int b = gw >> 11;
    const float4* xr = (const float4*)(x + (size_t)gw * Dd);
    const float4* o0 = (const float4*)(x + ((size_t)b * Ss + 2) * Dd);
    const float4* o1 = (const float4*)(x + ((size_t)b * Ss + 4) * Dd);
    const float4* o2 = (const float4*)(x + ((size_t)b * Ss + 6) * Dd);
    const float4* o3 = (const float4*)(x + ((size_t)b * Ss + 8) * Dd);
    float a0 = 0.f, a1 = 0.f, a2 = 0.f, a3 = 0.f;
    for (int j = lane; j < Dd / 4; j += 32) {
        float4 xv = xr[j];
        float4 v;
        v = o0[j]; a0 += xv.x * v.x + xv.y * v.y + xv.z * v.z + xv.w * v.w;
        v = o1[j]; a1 += xv.x * v.x + xv.y * v.y + xv.z * v.z + xv.w * v.w;
        v = o2[j]; a2 += xv.x * v.x + xv.y * v.y + xv.z * v.z + xv.w * v.w;
        v = o3[j]; a3 += xv.x * v.x + xv.y * v.y + xv.z * v.z + xv.w * v.w;
    }
    #pragma unroll
    for (int off = 16; off; off >>= 1) {
        a0 += __shfl_xor_sync(0xFFFFFFFFu, a0, off);
        a1 += __shfl_xor_sync(0xFFFFFFFFu, a1, off);
        a2 += __shfl_xor_sync(0xFFFFFFFFu, a2, off);
        a3 += __shfl_xor_sync(0xFFFFFFFFu, a3, off);
    }
    if (lane == 0) {
        g_U1[gw * 4 + 0] = a0;
        g_U1[gw * 4 + 1] = a1;
        g_U1[gw * 4 + 2] = a2;
        g_U1[gw * 4 + 3] = a3;
    }
}

// ---------------------------------------------------------------------------
// V[b,s,r,k] = sum_j h[b,s,k*1024+j] * x[b,10+2r,j]; h from g_hh (fp16)
// ---------------------------------------------------------------------------
__global__ void v_kernel(const float* __restrict__ x) {
    int gw = (blockIdx.x * blockDim.x + threadIdx.x) >> 5;
    int lane = threadIdx.x & 31;
    if (gw >= MM) return;
    int b = gw >> 11;
    const float2* od[4];
    #pragma unroll
    for (int r = 0; r < 4; r++)
        od[r] = (const float2*)(x + ((size_t)b * Ss + 10 + 2 * r) * Dd);
    float acc[16];
    #pragma unroll
    for (int i = 0; i < 16; i++) acc[i] = 0.f;
    #pragma unroll
    for (int k = 0; k < 4; k++) {
        const __half2* hh = (const __half2*)(g_hh + (size_t)gw * Hh + k * 1024);
        for (int j = lane; j < 512; j += 32) {
            float2 hv = __half22float2(hh[j]);
            #pragma unroll
            for (int r = 0; r < 4; r++) {
                float2 ov = od[r][j];
                acc[r * 4 + k] += hv.x * ov.x + hv.y * ov.y;
            }
        }
    }
    #pragma unroll
    for (int i = 0; i < 16; i++) {
        #pragma unroll
        for (int off = 16; off; off >>= 1)
            acc[i] += __shfl_xor_sync(0xFFFFFFFFu, acc[i], off);
    }
    if (lane == 0) {
        #pragma unroll
        for (int i = 0; i < 16; i++) g_V[gw * 16 + i] = acc[i];
    }
}

// ---------------------------------------------------------------------------
// GEMM1: h = gelu(x@W1^T + scale*lora1 + b1) -> fp16 g_hh
// ---------------------------------------------------------------------------
__global__ __launch_bounds__(256, 2)
void gemm1_mma(const float* __restrict__ x, const float* __restrict__ b1,
               const float* __restrict__ scale_p) {
    int m0 = blockIdx.y * 128, n0 = blockIdx.x * 128;
    float acc[4][4][4];
    gemm_f16<Dd>(g_xh, g_w1h, m0, n0, acc);

    int lane = threadIdx.x & 31, wid = threadIdx.x >> 5;
    int wm = wid >> 2, wn = wid & 3;
    float sc = *scale_p;
    int r = n0 >> 10;
    #pragma unroll
    for (int mi = 0; mi < 4; mi++) {
        #pragma unroll
        for (int half = 0; half < 2; half++) {
            int m = m0 + wm * 64 + mi * 16 + (lane >> 2) + half * 8;
            int b = m >> 11;
            float u = sc * g_U1[m * 4 + r];
            const float* ev = x + ((size_t)b * Ss + 1 + 2 * r) * Dd;
            #pragma unroll
            for (int ni = 0; ni < 4; ni++) {
                int n = n0 + wn * 32 + ni * 8 + 2 * (lane & 3);
                int nc = n & 1023;
                float c0 = acc[mi][ni][half * 2 + 0] + u * ev[nc]     + b1[n];
                float c1 = acc[mi][ni][half * 2 + 1] + u * ev[nc + 1] + b1[n + 1];
                *(__half2*)(g_hh + (size_t)m * Hh + n) =
                    __floats2half2_rn(gelu_exact(c0), gelu_exact(c1));
            }
        }
    }
}

// ---------------------------------------------------------------------------
// GEMM2: out = h@W2^T + scale*lora2 + b2  (fp32 out)
// ---------------------------------------------------------------------------
__global__ __launch_bounds__(256, 2)
void gemm2_mma(const float* __restrict__ x, const float* __restrict__ b2,
               const float* __restrict__ scale_p, float* __restrict__ out) {
    int m0 = blockIdx.y * 128, n0 = blockIdx.x * 128;
    float acc[4][4][4];
    gemm_f16<Hh>(g_hh, g_w2h, m0, n0, acc);

    int lane = threadIdx.x & 31, wid = threadIdx.x >> 5;
    int wm = wid >> 2, wn = wid & 3;
    float sc = *scale_p;
    int r = n0 >> 8;
    #pragma unroll
    for (int mi = 0; mi < 4; mi++) {
        #pragma unroll
        for (int half = 0; half < 2; half++) {
            int m = m0 + wm * 64 + mi * 16 + (lane >> 2) + half * 8;
            int b = m >> 11;
            float4 vv = *(const float4*)&g_V[m * 16 + r * 4];
            const float4* ev2 = (const float4*)(x + ((size_t)b * Ss + 9 + 2 * r) * Dd);
            #pragma unroll
            for (int ni = 0; ni < 4; ni++) {
                int n = n0 + wn * 32 + ni * 8 + 2 * (lane & 3);
                float4 e0 = ev2[n & 255];
                float4 e1 = ev2[(n + 1) & 255];
                float lora0 = vv.x * e0.x + vv.y * e0.y + vv.z * e0.z + vv.w * e0.w;
                float lora1 = vv.x * e1.x + vv.y * e1.y + vv.z * e1.z + vv.w * e1.w;
                float2 o;
                o.x = acc[mi][ni][half * 2 + 0] + sc * lora0 + b2[n];
                o.y = acc[mi][ni][half * 2 + 1] + sc * lora1 + b2[n + 1];
                *(float2*)(out + (size_t)m * Dd + n) = o;
            }
        }
    }
}

// ---------------------------------------------------------------------------
extern "C" void kernel_launch(void* const* d_in, const int* in_sizes, int n_in,
                              void* d_out, int out_size) {
    const float* x     = (const float*)d_in[0];
    const float* W1    = (const float*)d_in[1];
    const float* b1    = (const float*)d_in[2];
    const float* W2    = (const float*)d_in[3];
    const float* b2    = (const float*)d_in[4];
    const float* scale = (const float*)d_in[5];
    float* out = (float*)d_out;

    cudaFuncSetAttribute(gemm1_mma, cudaFuncAttributeMaxDynamicSharedMemorySize, SMEM_TOTAL);
    cudaFuncSetAttribute(gemm2_mma, cudaFuncAttributeMaxDynamicSharedMemorySize, SMEM_TOTAL);

    __half *xh, *w1h, *w2h;
    cudaGetSymbolAddress((void**)&xh, g_xh);
    cudaGetSymbolAddress((void**)&w1h, g_w1h);
    cudaGetSymbolAddress((void**)&w2h, g_w2h);

    u1_kernel<<<MM / 8, 256>>>(x);

    cvt_f16_kernel<<<(MM * Dd / 4 + 255) / 256, 256>>>(x, xh, MM * Dd / 4);
    cvt_f16_kernel<<<(Hh * Dd / 4 + 255) / 256, 256>>>(W1, w1h, Hh * Dd / 4);
    cvt_f16_kernel<<<(Dd * Hh / 4 + 255) / 256, 256>>>(W2, w2h, Dd * Hh / 4);

    dim3 g1(Hh / 128, MM / 128);   // (32, 64)
    gemm1_mma<<<g1, 256, SMEM_TOTAL>>>(x, b1, scale);

    v_kernel<<<MM / 8, 256>>>(x);

    dim3 g2(Dd / 128, MM / 128);   // (8, 64)
    gemm2_mma<<<g2, 256, SMEM_TOTAL>>>(x, b2, scale, out);
}

// round 15
// speedup vs baseline: 1.2436x; 1.1003x over previous
#include <cuda_runtime.h>
#include <cuda_fp16.h>
#include <math.h>
#include <stdint.h>

// Problem constants
#define Bb 4
#define Ss 2048
#define Dd 1024
#define Hh 4096
#define MM (Bb * Ss)   // 8192

// ---------------------------------------------------------------------------
// Device-global scratch (allocation-free rule). fp16 (rn-rounded) operands.
// ---------------------------------------------------------------------------
__device__ __half g_xh[(size_t)MM * Dd];
__device__ __half g_w1h[(size_t)Hh * Dd];
__device__ __half g_w2h[(size_t)Dd * Hh];
__device__ __half g_hh[(size_t)MM * Hh];   // post-GELU hidden, fp16
__device__ float g_U1[MM * 4];
__device__ float g_V[MM * 16];

__device__ __forceinline__ float gelu_exact(float v) {
    return 0.5f * v * (1.0f + erff(v * 0.70710678118654752f));
}

__device__ __forceinline__ uint32_t smem_u32(const void* p) {
    uint32_t a;
    asm("{ .reg .u64 t; cvta.to.shared.u64 t, %1; cvt.u32.u64 %0, t; }"
        : "=r"(a) : "l"(p));
    return a;
}

// ---------------------------------------------------------------------------
// fp16 mma / ldmatrix / cp.async primitives
// ---------------------------------------------------------------------------
__device__ __forceinline__ void mma16816h(float* d, const uint32_t* a, const uint32_t* b) {
    asm volatile(
        "mma.sync.aligned.m16n8k16.row.col.f32.f16.f16.f32 "
        "{%0,%1,%2,%3}, {%4,%5,%6,%7}, {%8,%9}, {%0,%1,%2,%3};"
        : "+f"(d[0]), "+f"(d[1]), "+f"(d[2]), "+f"(d[3])
        : "r"(a[0]), "r"(a[1]), "r"(a[2]), "r"(a[3]), "r"(b[0]), "r"(b[1]));
}

__device__ __forceinline__ void ldm4(uint32_t* r, uint32_t addr) {
    asm volatile("ldmatrix.sync.aligned.m8n8.x4.shared.b16 {%0,%1,%2,%3}, [%4];"
                 : "=r"(r[0]), "=r"(r[1]), "=r"(r[2]), "=r"(r[3]) : "r"(addr));
}

__device__ __forceinline__ void cp16(uint32_t s, const void* g) {
    asm volatile("cp.async.cg.shared.global [%0], [%1], 16;" :: "r"(s), "l"(g));
}
__device__ __forceinline__ void cp_commit() {
    asm volatile("cp.async.commit_group;" ::: "memory");
}
template <int N>
__device__ __forceinline__ void cp_wait() {
    asm volatile("cp.async.wait_group %0;" :: "n"(N) : "memory");
}

// ---------------------------------------------------------------------------
// Tiling: 128x128 CTA tile, BK=64 fp16, 3-stage ring, one sync per chunk,
// cp.async issue INTERLEAVED into the MMA stream. 2 CTAs/SM.
// ---------------------------------------------------------------------------
#define BK 64
#define TSTRIDE 144                   // 64 fp16 = 128 B data + 16 B pad
#define TILE_B (128 * TSTRIDE)        // 18432 B per tile
#define STAGE_B (2 * TILE_B)          // A + B = 36864 B per stage
#define NSTAGE 3
#define SMEM_TOTAL (NSTAGE * STAGE_B) // 110592 B

extern __shared__ char dsmem[];

// Issue cp.async for one BK=64 chunk in one burst (prologue only).
__device__ __forceinline__ void issue_chunk(
    uint32_t sbuf, const __half* __restrict__ Ah, const __half* __restrict__ Bh,
    int m0, int n0, int kc, int KDIM, int tid)
{
    #pragma unroll
    for (int i = 0; i < 4; i++) {
        int idx = tid + i * 256;
        int row = idx >> 3, c = idx & 7;
        uint32_t soff = (uint32_t)(row * TSTRIDE + c * 16);
        size_t ga = (size_t)(m0 + row) * KDIM + kc * BK + c * 8;
        size_t gb = (size_t)(n0 + row) * KDIM + kc * BK + c * 8;
        cp16(sbuf + soff, Ah + ga);
        cp16(sbuf + TILE_B + soff, Bh + gb);
    }
}

// Load 4 A fragments (64 rows x k16) from a tile.
__device__ __forceinline__ void lda(uint32_t a[4][4], uint32_t tile, int wm, int lane, int ks) {
    uint32_t koff = (uint32_t)(ks * 32 + (lane >> 4) * 16);
    #pragma unroll
    for (int mi = 0; mi < 4; mi++) {
        uint32_t addr = tile + (uint32_t)((wm * 64 + mi * 16 + (lane & 15)) * TSTRIDE) + koff;
        ldm4(a[mi], addr);
    }
}

// Load 4 B fragments (32 cols x k16) from a tile.
__device__ __forceinline__ void ldb(uint32_t b[4][2], uint32_t tile, int wn, int lane, int ks) {
    #pragma unroll
    for (int g = 0; g < 2; g++) {
        int nrow = wn * 32 + g * 16 + (lane & 7) + ((lane >> 4) & 1) * 8;
        uint32_t addr = tile + (uint32_t)(nrow * TSTRIDE) +
                        (uint32_t)(ks * 32 + ((lane >> 3) & 1) * 16);
        uint32_t r[4];
        ldm4(r, addr);
        b[2 * g][0] = r[0]; b[2 * g][1] = r[1];
        b[2 * g + 1][0] = r[2]; b[2 * g + 1][1] = r[3];
    }
}

// One BK=64 chunk with chunk-(c+2) cp.async issue interleaved: per ks
// iteration 2 cp16 + 6 LDSM + 16 MMA. Commit happens in the caller.
__device__ __forceinline__ void compute_chunk_fused(
    uint32_t sbuf, int wm, int wn, int lane, float acc[4][4][4],
    bool do_issue, uint32_t sbuf_n,
    const __half* __restrict__ Ah, const __half* __restrict__ Bh,
    int m0, int n0, int kc, int KDIM, int tid)
{
    #pragma unroll
    for (int ks = 0; ks < 4; ks++) {
        if (do_issue) {
            int idx = tid + ks * 256;
            int row = idx >> 3, c = idx & 7;
            uint32_t soff = (uint32_t)(row * TSTRIDE + c * 16);
            size_t ga = (size_t)(m0 + row) * KDIM + kc * BK + c * 8;
            size_t gb = (size_t)(n0 + row) * KDIM + kc * BK + c * 8;
            cp16(sbuf_n + soff, Ah + ga);
            cp16(sbuf_n + TILE_B + soff, Bh + gb);
        }
        uint32_t a[4][4], b[4][2];
        lda(a, sbuf, wm, lane, ks);
        ldb(b, sbuf + TILE_B, wn, lane, ks);
        #pragma unroll
        for (int mi = 0; mi < 4; mi++)
            #pragma unroll
            for (int ni = 0; ni < 4; ni++)
                mma16816h(acc[mi][ni], a[mi], b[ni]);
    }
}

// Mainloop: 3-stage ring, prefetch depth 2, one sync per chunk, interleaved
// issue. Sync safety: the barrier before compute(c) certifies all warps done
// with compute(c-1); the interleaved issue overwrites stage (c+2)%3 ==
// (c-1)%3 — exactly the guarded stage. The same barrier publishes the
// cp.async arrivals of stage c (retired by cp_wait just before it).
template <int KDIM>
__device__ __forceinline__ void gemm_f16(
    const __half* __restrict__ Ah, const __half* __restrict__ Bh,
    int m0, int n0, float acc[4][4][4])
{
    int tid = threadIdx.x;
    int lane = tid & 31, wid = tid >> 5;
    int wm = wid >> 2, wn = wid & 3;
    uint32_t sbase = smem_u32(dsmem);

    #pragma unroll
    for (int mi = 0; mi < 4; mi++)
        #pragma unroll
        for (int ni = 0; ni < 4; ni++)
            #pragma unroll
            for (int q = 0; q < 4; q++) acc[mi][ni][q] = 0.f;

    const int NC = KDIM / BK;
    issue_chunk(sbase + 0 * STAGE_B, Ah, Bh, m0, n0, 0, KDIM, tid);
    cp_commit();
    issue_chunk(sbase + 1 * STAGE_B, Ah, Bh, m0, n0, 1, KDIM, tid);
    cp_commit();

    int st_c = 0;
    for (int c = 0; c < NC; c++) {
        if (c + 1 < NC) cp_wait<1>();     // outstanding {c, c+1} -> c retired
        else            cp_wait<0>();
        __syncthreads();
        bool di = (c + 2 < NC);
        int st_n = st_c + 2; if (st_n >= NSTAGE) st_n -= NSTAGE;
        compute_chunk_fused(sbase + st_c * STAGE_B, wm, wn, lane, acc,
                            di, sbase + st_n * STAGE_B,
                            Ah, Bh, m0, n0, c + 2, KDIM, tid);
        if (di) cp_commit();
        if (++st_c == NSTAGE) st_c = 0;
    }
}

// ---------------------------------------------------------------------------
// cvt: fp32 -> fp16 for x, W1, W2 in ONE launch (segmented index space)
// ---------------------------------------------------------------------------
#define N4_X  (MM * Dd / 4)   // 2097152
#define N4_W1 (Hh * Dd / 4)   // 1048576
#define N4_W2 (Dd * Hh / 4)   // 1048576
#define N4_ALL (N4_X + N4_W1 + N4_W2)

__global__ void cvt_all_kernel(const float* __restrict__ x,
                               const float* __restrict__ W1,
                               const float* __restrict__ W2,
                               __half* __restrict__ xh,
                               __half* __restrict__ w1h,
                               __half* __restrict__ w2h) {
    int i = blockIdx.x * blockDim.x + threadIdx.x;
    if (i >= N4_ALL) return;
    const float* src;
    __half* dst;
    int j;
    if (i < N4_X)            { src = x;  dst = xh;  j = i; }
    else if (i < N4_X + N4_W1) { src = W1; dst = w1h; j = i - N4_X; }
    else                     { src = W2; dst = w2h; j = i - N4_X - N4_W1; }
    float4 v = ((const float4*)src)[j];
    __half2* d = (__half2*)dst;
    d[2 * j]     = __floats2half2_rn(v.x, v.y);
    d[2 * j + 1] = __floats2half2_rn(v.z, v.w);
}

// ---------------------------------------------------------------------------
// U1[b,s,r] = x[b,s,:] . x[b, 2+2r, :]  (fp32 exact); 1 warp/(b,s)
// ---------------------------------------------------------------------------
__global__ void u1_kernel(const float* __restrict__ x) {
    int gw = (blockIdx.x * blockDim.x + threadIdx.x) >> 5;
    int lane = threadIdx.x & 31;
    if (gw >= MM) return;
    int b = gw >> 11;
    const float4* xr = (const float4*)(x + (size_t)gw * Dd);
    const float4* o0 = (const float4*)(x + ((size_t)b * Ss + 2) * Dd);
    const float4* o1 = (const float4*)(x + ((size_t)b * Ss + 4) * Dd);
    const float4* o2 = (const float4*)(x + ((size_t)b * Ss + 6) * Dd);
    const float4* o3 = (const float4*)(x + ((size_t)b * Ss + 8) * Dd);
    float a0 = 0.f, a1 = 0.f, a2 = 0.f, a3 = 0.f;
    for (int j = lane; j < Dd / 4; j += 32) {
        float4 xv = xr[j];
        float4 v;
        v = o0[j]; a0 += xv.x * v.x + xv.y * v.y + xv.z * v.z + xv.w * v.w;
        v = o1[j]; a1 += xv.x * v.x + xv.y * v.y + xv.z * v.z + xv.w * v.w;
        v = o2[j]; a2 += xv.x * v.x + xv.y * v.y + xv.z * v.z + xv.w * v.w;
        v = o3[j]; a3 += xv.x * v.x + xv.y * v.y + xv.z * v.z + xv.w * v.w;
    }
    #pragma unroll
    for (int off = 16; off; off >>= 1) {
        a0 += __shfl_xor_sync(0xFFFFFFFFu, a0, off);
        a1 += __shfl_xor_sync(0xFFFFFFFFu, a1, off);
        a2 += __shfl_xor_sync(0xFFFFFFFFu, a2, off);
        a3 += __shfl_xor_sync(0xFFFFFFFFu, a3, off);
    }
    if (lane == 0) {
        g_U1[gw * 4 + 0] = a0;
        g_U1[gw * 4 + 1] = a1;
        g_U1[gw * 4 + 2] = a2;
        g_U1[gw * 4 + 3] = a3;
    }
}

// ---------------------------------------------------------------------------
// V[b,s,r,k] = sum_j h[b,s,k*1024+j] * x[b,10+2r,j]; h from g_hh (fp16)
// ---------------------------------------------------------------------------
__global__ void v_kernel(const float* __restrict__ x) {
    int gw = (blockIdx.x * blockDim.x + threadIdx.x) >> 5;
    int lane = threadIdx.x & 31;
    if (gw >= MM) return;
    int b = gw >> 11;
    const float2* od[4];
    #pragma unroll
    for (int r = 0; r < 4; r++)
        od[r] = (const float2*)(x + ((size_t)b * Ss + 10 + 2 * r) * Dd);
    float acc[16];
    #pragma unroll
    for (int i = 0; i < 16; i++) acc[i] = 0.f;
    #pragma unroll
    for (int k = 0; k < 4; k++) {
        const __half2* hh = (const __half2*)(g_hh + (size_t)gw * Hh + k * 1024);
        for (int j = lane; j < 512; j += 32) {
            float2 hv = __half22float2(hh[j]);
            #pragma unroll
            for (int r = 0; r < 4; r++) {
                float2 ov = od[r][j];
                acc[r * 4 + k] += hv.x * ov.x + hv.y * ov.y;
            }
        }
    }
    #pragma unroll
    for (int i = 0; i < 16; i++) {
        #pragma unroll
        for (int off = 16; off; off >>= 1)
            acc[i] += __shfl_xor_sync(0xFFFFFFFFu, acc[i], off);
    }
    if (lane == 0) {
        #pragma unroll
        for (int i = 0; i < 16; i++) g_V[gw * 16 + i] = acc[i];
    }
}

// ---------------------------------------------------------------------------
// GEMM1: h = gelu(x@W1^T + scale*lora1 + b1) -> fp16 g_hh
// ---------------------------------------------------------------------------
__global__ __launch_bounds__(256, 2)
void gemm1_mma(const float* __restrict__ x, const float* __restrict__ b1,
               const float* __restrict__ scale_p) {
    int m0 = blockIdx.y * 128, n0 = blockIdx.x * 128;
    float acc[4][4][4];
    gemm_f16<Dd>(g_xh, g_w1h, m0, n0, acc);

    int lane = threadIdx.x & 31, wid = threadIdx.x >> 5;
    int wm = wid >> 2, wn = wid & 3;
    float sc = *scale_p;
    int r = n0 >> 10;
    #pragma unroll
    for (int mi = 0; mi < 4; mi++) {
        #pragma unroll
        for (int half = 0; half < 2; half++) {
            int m = m0 + wm * 64 + mi * 16 + (lane >> 2) + half * 8;
            int b = m >> 11;
            float u = sc * g_U1[m * 4 + r];
            const float* ev = x + ((size_t)b * Ss + 1 + 2 * r) * Dd;
            #pragma unroll
            for (int ni = 0; ni < 4; ni++) {
                int n = n0 + wn * 32 + ni * 8 + 2 * (lane & 3);
                int nc = n & 1023;
                float c0 = acc[mi][ni][half * 2 + 0] + u * ev[nc]     + b1[n];
                float c1 = acc[mi][ni][half * 2 + 1] + u * ev[nc + 1] + b1[n + 1];
                *(__half2*)(g_hh + (size_t)m * Hh + n) =
                    __floats2half2_rn(gelu_exact(c0), gelu_exact(c1));
            }
        }
    }
}

// ---------------------------------------------------------------------------
// GEMM2: out = h@W2^T + scale*lora2 + b2  (fp32 out)
// ---------------------------------------------------------------------------
__global__ __launch_bounds__(256, 2)
void gemm2_mma(const float* __restrict__ x, const float* __restrict__ b2,
               const float* __restrict__ scale_p, float* __restrict__ out) {
    int m0 = blockIdx.y * 128, n0 = blockIdx.x * 128;
    float acc[4][4][4];
    gemm_f16<Hh>(g_hh, g_w2h, m0, n0, acc);

    int lane = threadIdx.x & 31, wid = threadIdx.x >> 5;
    int wm = wid >> 2, wn = wid & 3;
    float sc = *scale_p;
    int r = n0 >> 8;
    #pragma unroll
    for (int mi = 0; mi < 4; mi++) {
        #pragma unroll
        for (int half = 0; half < 2; half++) {
            int m = m0 + wm * 64 + mi * 16 + (lane >> 2) + half * 8;
            int b = m >> 11;
            float4 vv = *(const float4*)&g_V[m * 16 + r * 4];
            const float4* ev2 = (const float4*)(x + ((size_t)b * Ss + 9 + 2 * r) * Dd);
            #pragma unroll
            for (int ni = 0; ni < 4; ni++) {
                int n = n0 + wn * 32 + ni * 8 + 2 * (lane & 3);
                float4 e0 = ev2[n & 255];
                float4 e1 = ev2[(n + 1) & 255];
                float lora0 = vv.x * e0.x + vv.y * e0.y + vv.z * e0.z + vv.w * e0.w;
                float lora1 = vv.x * e1.x + vv.y * e1.y + vv.z * e1.z + vv.w * e1.w;
                float2 o;
                o.x = acc[mi][ni][half * 2 + 0] + sc * lora0 + b2[n];
                o.y = acc[mi][ni][half * 2 + 1] + sc * lora1 + b2[n + 1];
                *(float2*)(out + (size_t)m * Dd + n) = o;
            }
        }
    }
}

// ---------------------------------------------------------------------------
extern "C" void kernel_launch(void* const* d_in, const int* in_sizes, int n_in,
                              void* d_out, int out_size) {
    const float* x     = (const float*)d_in[0];
    const float* W1    = (const float*)d_in[1];
    const float* b1    = (const float*)d_in[2];
    const float* W2    = (const float*)d_in[3];
    const float* b2    = (const float*)d_in[4];
    const float* scale = (const float*)d_in[5];
    float* out = (float*)d_out;

    cudaFuncSetAttribute(gemm1_mma, cudaFuncAttributeMaxDynamicSharedMemorySize, SMEM_TOTAL);
    cudaFuncSetAttribute(gemm2_mma, cudaFuncAttributeMaxDynamicSharedMemorySize, SMEM_TOTAL);

    __half *xh, *w1h, *w2h;
    cudaGetSymbolAddress((void**)&xh, g_xh);
    cudaGetSymbolAddress((void**)&w1h, g_w1h);
    cudaGetSymbolAddress((void**)&w2h, g_w2h);

    u1_kernel<<<MM / 8, 256>>>(x);

    cvt_all_kernel<<<(N4_ALL + 255) / 256, 256>>>(x, W1, W2, xh, w1h, w2h);

    dim3 g1(Hh / 128, MM / 128);   // (32, 64)
    gemm1_mma<<<g1, 256, SMEM_TOTAL>>>(x, b1, scale);

    v_kernel<<<MM / 8, 256>>>(x);

    dim3 g2(Dd / 128, MM / 128);   // (8, 64)
    gemm2_mma<<<g2, 256, SMEM_TOTAL>>>(x, b2, scale, out);
}

// round 16
// speedup vs baseline: 1.2964x; 1.0425x over previous
#include <cuda_runtime.h>
#include <cuda_fp16.h>
#include <math.h>
#include <stdint.h>

// Problem constants
#define Bb 4
#define Ss 2048
#define Dd 1024
#define Hh 4096
#define MM (Bb * Ss)   // 8192

// ---------------------------------------------------------------------------
// Device-global scratch (allocation-free rule). fp16 (rn-rounded) operands.
// ---------------------------------------------------------------------------
__device__ __half g_xh[(size_t)MM * Dd];
__device__ __half g_w1h[(size_t)Hh * Dd];
__device__ __half g_w2h[(size_t)Dd * Hh];
__device__ __half g_hh[(size_t)MM * Hh];   // post-GELU hidden, fp16
__device__ float g_U1[MM * 4];
__device__ float g_V[MM * 16];

__device__ __forceinline__ float gelu_exact(float v) {
    return 0.5f * v * (1.0f + erff(v * 0.70710678118654752f));
}

__device__ __forceinline__ uint32_t smem_u32(const void* p) {
    uint32_t a;
    asm("{ .reg .u64 t; cvta.to.shared.u64 t, %1; cvt.u32.u64 %0, t; }"
        : "=r"(a) : "l"(p));
    return a;
}

// ---------------------------------------------------------------------------
// fp16 mma / ldmatrix / cp.async primitives
// ---------------------------------------------------------------------------
__device__ __forceinline__ void mma16816h(float* d, const uint32_t* a, const uint32_t* b) {
    asm volatile(
        "mma.sync.aligned.m16n8k16.row.col.f32.f16.f16.f32 "
        "{%0,%1,%2,%3}, {%4,%5,%6,%7}, {%8,%9}, {%0,%1,%2,%3};"
        : "+f"(d[0]), "+f"(d[1]), "+f"(d[2]), "+f"(d[3])
        : "r"(a[0]), "r"(a[1]), "r"(a[2]), "r"(a[3]), "r"(b[0]), "r"(b[1]));
}

__device__ __forceinline__ void ldm4(uint32_t* r, uint32_t addr) {
    asm volatile("ldmatrix.sync.aligned.m8n8.x4.shared.b16 {%0,%1,%2,%3}, [%4];"
                 : "=r"(r[0]), "=r"(r[1]), "=r"(r[2]), "=r"(r[3]) : "r"(addr));
}

__device__ __forceinline__ void cp16(uint32_t s, const void* g) {
    asm volatile("cp.async.cg.shared.global [%0], [%1], 16;" :: "r"(s), "l"(g));
}
__device__ __forceinline__ void cp_commit() {
    asm volatile("cp.async.commit_group;" ::: "memory");
}
template <int N>
__device__ __forceinline__ void cp_wait() {
    asm volatile("cp.async.wait_group %0;" :: "n"(N) : "memory");
}

// ---------------------------------------------------------------------------
// GEMM tiling (R15 champion, unchanged): 128x128 tile, BK=64, 3-stage ring,
// one sync per chunk, interleaved cp.async issue, 2 CTAs/SM.
// ---------------------------------------------------------------------------
#define BK 64
#define TSTRIDE 144
#define TILE_B (128 * TSTRIDE)
#define STAGE_B (2 * TILE_B)
#define NSTAGE 3
#define SMEM_TOTAL (NSTAGE * STAGE_B) // 110592 B

extern __shared__ char dsmem[];

__device__ __forceinline__ void issue_chunk(
    uint32_t sbuf, const __half* __restrict__ Ah, const __half* __restrict__ Bh,
    int m0, int n0, int kc, int KDIM, int tid)
{
    #pragma unroll
    for (int i = 0; i < 4; i++) {
        int idx = tid + i * 256;
        int row = idx >> 3, c = idx & 7;
        uint32_t soff = (uint32_t)(row * TSTRIDE + c * 16);
        size_t ga = (size_t)(m0 + row) * KDIM + kc * BK + c * 8;
        size_t gb = (size_t)(n0 + row) * KDIM + kc * BK + c * 8;
        cp16(sbuf + soff, Ah + ga);
        cp16(sbuf + TILE_B + soff, Bh + gb);
    }
}

__device__ __forceinline__ void lda(uint32_t a[4][4], uint32_t tile, int wm, int lane, int ks) {
    uint32_t koff = (uint32_t)(ks * 32 + (lane >> 4) * 16);
    #pragma unroll
    for (int mi = 0; mi < 4; mi++) {
        uint32_t addr = tile + (uint32_t)((wm * 64 + mi * 16 + (lane & 15)) * TSTRIDE) + koff;
        ldm4(a[mi], addr);
    }
}

__device__ __forceinline__ void ldb(uint32_t b[4][2], uint32_t tile, int wn, int lane, int ks) {
    #pragma unroll
    for (int g = 0; g < 2; g++) {
        int nrow = wn * 32 + g * 16 + (lane & 7) + ((lane >> 4) & 1) * 8;
        uint32_t addr = tile + (uint32_t)(nrow * TSTRIDE) +
                        (uint32_t)(ks * 32 + ((lane >> 3) & 1) * 16);
        uint32_t r[4];
        ldm4(r, addr);
        b[2 * g][0] = r[0]; b[2 * g][1] = r[1];
        b[2 * g + 1][0] = r[2]; b[2 * g + 1][1] = r[3];
    }
}

__device__ __forceinline__ void compute_chunk_fused(
    uint32_t sbuf, int wm, int wn, int lane, float acc[4][4][4],
    bool do_issue, uint32_t sbuf_n,
    const __half* __restrict__ Ah, const __half* __restrict__ Bh,
    int m0, int n0, int kc, int KDIM, int tid)
{
    #pragma unroll
    for (int ks = 0; ks < 4; ks++) {
        if (do_issue) {
            int idx = tid + ks * 256;
            int row = idx >> 3, c = idx & 7;
            uint32_t soff = (uint32_t)(row * TSTRIDE + c * 16);
            size_t ga = (size_t)(m0 + row) * KDIM + kc * BK + c * 8;
            size_t gb = (size_t)(n0 + row) * KDIM + kc * BK + c * 8;
            cp16(sbuf_n + soff, Ah + ga);
            cp16(sbuf_n + TILE_B + soff, Bh + gb);
        }
        uint32_t a[4][4], b[4][2];
        lda(a, sbuf, wm, lane, ks);
        ldb(b, sbuf + TILE_B, wn, lane, ks);
        #pragma unroll
        for (int mi = 0; mi < 4; mi++)
            #pragma unroll
            for (int ni = 0; ni < 4; ni++)
                mma16816h(acc[mi][ni], a[mi], b[ni]);
    }
}

template <int KDIM>
__device__ __forceinline__ void gemm_f16(
    const __half* __restrict__ Ah, const __half* __restrict__ Bh,
    int m0, int n0, float acc[4][4][4])
{
    int tid = threadIdx.x;
    int lane = tid & 31, wid = tid >> 5;
    int wm = wid >> 2, wn = wid & 3;
    uint32_t sbase = smem_u32(dsmem);

    #pragma unroll
    for (int mi = 0; mi < 4; mi++)
        #pragma unroll
        for (int ni = 0; ni < 4; ni++)
            #pragma unroll
            for (int q = 0; q < 4; q++) acc[mi][ni][q] = 0.f;

    const int NC = KDIM / BK;
    issue_chunk(sbase + 0 * STAGE_B, Ah, Bh, m0, n0, 0, KDIM, tid);
    cp_commit();
    issue_chunk(sbase + 1 * STAGE_B, Ah, Bh, m0, n0, 1, KDIM, tid);
    cp_commit();

    int st_c = 0;
    for (int c = 0; c < NC; c++) {
        if (c + 1 < NC) cp_wait<1>();
        else            cp_wait<0>();
        __syncthreads();
        bool di = (c + 2 < NC);
        int st_n = st_c + 2; if (st_n >= NSTAGE) st_n -= NSTAGE;
        compute_chunk_fused(sbase + st_c * STAGE_B, wm, wn, lane, acc,
                            di, sbase + st_n * STAGE_B,
                            Ah, Bh, m0, n0, c + 2, KDIM, tid);
        if (di) cp_commit();
        if (++st_c == NSTAGE) st_c = 0;
    }
}

// ---------------------------------------------------------------------------
// cvt: fp32 -> fp16 for x, W1, W2 in one launch; 2 independent float4/thread
// (segment split lands exactly at N4_X so both halves are branch-uniform).
// ---------------------------------------------------------------------------
#define N4_X  (MM * Dd / 4)   // 2097152
#define N4_W1 (Hh * Dd / 4)   // 1048576
#define N4_W2 (Dd * Hh / 4)   // 1048576
#define N4_ALL (N4_X + N4_W1 + N4_W2)
#define N4_HALF (N4_ALL / 2)  // == N4_X

__global__ void cvt_all_kernel(const float* __restrict__ x,
                               const float* __restrict__ W1,
                               const float* __restrict__ W2,
                               __half* __restrict__ xh,
                               __half* __restrict__ w1h,
                               __half* __restrict__ w2h) {
    int i = blockIdx.x * blockDim.x + threadIdx.x;
    if (i >= N4_HALF) return;
    // slot 0: x[i]; slot 1: W1/W2 region at j = i
    float4 v0 = ((const float4*)x)[i];
    const float* src1; __half* dst1; int j1;
    if (i < N4_W1) { src1 = W1; dst1 = w1h; j1 = i; }
    else           { src1 = W2; dst1 = w2h; j1 = i - N4_W1; }
    float4 v1 = ((const float4*)src1)[j1];

    __half2* dx = (__half2*)xh;
    dx[2 * i]     = __floats2half2_rn(v0.x, v0.y);
    dx[2 * i + 1] = __floats2half2_rn(v0.z, v0.w);
    __half2* d1 = (__half2*)dst1;
    d1[2 * j1]     = __floats2half2_rn(v1.x, v1.y);
    d1[2 * j1 + 1] = __floats2half2_rn(v1.z, v1.w);
}

// ---------------------------------------------------------------------------
// U1[b,s,r] = x[b,s,:] . x[b, 2+2r, :]  (fp32); 1 warp/(b,s).
// Stream loads batched 4-deep for MLP.
// ---------------------------------------------------------------------------
__global__ void u1_kernel(const float* __restrict__ x) {
    int gw = (blockIdx.x * blockDim.x + threadIdx.x) >> 5;
    int lane = threadIdx.x & 31;
    if (gw >= MM) return;
    int b = gw >> 11;
    const float4* xr = (const float4*)(x + (size_t)gw * Dd);
    const float4* od[4];
    #pragma unroll
    for (int r = 0; r < 4; r++)
        od[r] = (const float4*)(x + ((size_t)b * Ss + 2 + 2 * r) * Dd);
    float a[4] = {0.f, 0.f, 0.f, 0.f};
    #pragma unroll
    for (int t0 = 0; t0 < 2; t0++) {
        float4 xv[4];
        #pragma unroll
        for (int t = 0; t < 4; t++)
            xv[t] = xr[lane + (t0 * 4 + t) * 32];     // 4 batched stream loads
        #pragma unroll
        for (int t = 0; t < 4; t++) {
            int j = lane + (t0 * 4 + t) * 32;
            #pragma unroll
            for (int r = 0; r < 4; r++) {
                float4 v = od[r][j];
                a[r] += xv[t].x * v.x + xv[t].y * v.y + xv[t].z * v.z + xv[t].w * v.w;
            }
        }
    }
    #pragma unroll
    for (int r = 0; r < 4; r++) {
        #pragma unroll
        for (int off = 16; off; off >>= 1)
            a[r] += __shfl_xor_sync(0xFFFFFFFFu, a[r], off);
    }
    if (lane == 0) {
        #pragma unroll
        for (int r = 0; r < 4; r++) g_U1[gw * 4 + r] = a[r];
    }
}

// ---------------------------------------------------------------------------
// V[b,s,r,k] = sum_j h[b,s,k*1024+j] * x[b,10+2r,j]; h streamed as uint4
// (16 B/lane), 4 loads batched per k-block for MLP.
// ---------------------------------------------------------------------------
__global__ void v_kernel(const float* __restrict__ x) {
    int gw = (blockIdx.x * blockDim.x + threadIdx.x) >> 5;
    int lane = threadIdx.x & 31;
    if (gw >= MM) return;
    int b = gw >> 11;
    const float4* od[4];
    #pragma unroll
    for (int r = 0; r < 4; r++)
        od[r] = (const float4*)(x + ((size_t)b * Ss + 10 + 2 * r) * Dd);
    float acc[16];
    #pragma unroll
    for (int i = 0; i < 16; i++) acc[i] = 0.f;

    const uint4* hr = (const uint4*)(g_hh + (size_t)gw * Hh);   // 512 uint4
    #pragma unroll
    for (int k = 0; k < 4; k++) {
        uint4 hv[4];
        #pragma unroll
        for (int t = 0; t < 4; t++)
            hv[t] = hr[k * 128 + lane + t * 32];     // 4 batched 16B h loads
        #pragma unroll
        for (int t = 0; t < 4; t++) {
            int j8 = lane + t * 32;                  // 8-half group index in k-block
            float2 f0 = __half22float2(*(const __half2*)&hv[t].x);
            float2 f1 = __half22float2(*(const __half2*)&hv[t].y);
            float2 f2 = __half22float2(*(const __half2*)&hv[t].z);
            float2 f3 = __half22float2(*(const __half2*)&hv[t].w);
            #pragma unroll
            for (int r = 0; r < 4; r++) {
                float4 x0 = od[r][2 * j8];
                float4 x1 = od[r][2 * j8 + 1];
                acc[r * 4 + k] += f0.x * x0.x + f0.y * x0.y + f1.x * x0.z + f1.y * x0.w
                                + f2.x * x1.x + f2.y * x1.y + f3.x * x1.z + f3.y * x1.w;
            }
        }
    }
    #pragma unroll
    for (int i = 0; i < 16; i++) {
        #pragma unroll
        for (int off = 16; off; off >>= 1)
            acc[i] += __shfl_xor_sync(0xFFFFFFFFu, acc[i], off);
    }
    if (lane == 0) {
        #pragma unroll
        for (int i = 0; i < 16; i++) g_V[gw * 16 + i] = acc[i];
    }
}

// ---------------------------------------------------------------------------
// GEMM1: h = gelu(x@W1^T + scale*lora1 + b1) -> fp16 g_hh
// ---------------------------------------------------------------------------
__global__ __launch_bounds__(256, 2)
void gemm1_mma(const float* __restrict__ x, const float* __restrict__ b1,
               const float* __restrict__ scale_p) {
    int m0 = blockIdx.y * 128, n0 = blockIdx.x * 128;
    float acc[4][4][4];
    gemm_f16<Dd>(g_xh, g_w1h, m0, n0, acc);

    int lane = threadIdx.x & 31, wid = threadIdx.x >> 5;
    int wm = wid >> 2, wn = wid & 3;
    float sc = *scale_p;
    int r = n0 >> 10;
    #pragma unroll
    for (int mi = 0; mi < 4; mi++) {
        #pragma unroll
        for (int half = 0; half < 2; half++) {
            int m = m0 + wm * 64 + mi * 16 + (lane >> 2) + half * 8;
            int b = m >> 11;
            float u = sc * g_U1[m * 4 + r];
            const float* ev = x + ((size_t)b * Ss + 1 + 2 * r) * Dd;
            #pragma unroll
            for (int ni = 0; ni < 4; ni++) {
                int n = n0 + wn * 32 + ni * 8 + 2 * (lane & 3);
                int nc = n & 1023;
                float c0 = acc[mi][ni][half * 2 + 0] + u * ev[nc]     + b1[n];
                float c1 = acc[mi][ni][half * 2 + 1] + u * ev[nc + 1] + b1[n + 1];
                *(__half2*)(g_hh + (size_t)m * Hh + n) =
                    __floats2half2_rn(gelu_exact(c0), gelu_exact(c1));
            }
        }
    }
}

// ---------------------------------------------------------------------------
// GEMM2: out = h@W2^T + scale*lora2 + b2  (fp32 out)
// ---------------------------------------------------------------------------
__global__ __launch_bounds__(256, 2)
void gemm2_mma(const float* __restrict__ x, const float* __restrict__ b2,
               const float* __restrict__ scale_p, float* __restrict__ out) {
    int m0 = blockIdx.y * 128, n0 = blockIdx.x * 128;
    float acc[4][4][4];
    gemm_f16<Hh>(g_hh, g_w2h, m0, n0, acc);

    int lane = threadIdx.x & 31, wid = threadIdx.x >> 5;
    int wm = wid >> 2, wn = wid & 3;
    float sc = *scale_p;
    int r = n0 >> 8;
    #pragma unroll
    for (int mi = 0; mi < 4; mi++) {
        #pragma unroll
        for (int half = 0; half < 2; half++) {
            int m = m0 + wm * 64 + mi * 16 + (lane >> 2) + half * 8;
            int b = m >> 11;
            float4 vv = *(const float4*)&g_V[m * 16 + r * 4];
            const float4* ev2 = (const float4*)(x + ((size_t)b * Ss + 9 + 2 * r) * Dd);
            #pragma unroll
            for (int ni = 0; ni < 4; ni++) {
                int n = n0 + wn * 32 + ni * 8 + 2 * (lane & 3);
                float4 e0 = ev2[n & 255];
                float4 e1 = ev2[(n + 1) & 255];
                float lora0 = vv.x * e0.x + vv.y * e0.y + vv.z * e0.z + vv.w * e0.w;
                float lora1 = vv.x * e1.x + vv.y * e1.y + vv.z * e1.z + vv.w * e1.w;
                float2 o;
                o.x = acc[mi][ni][half * 2 + 0] + sc * lora0 + b2[n];
                o.y = acc[mi][ni][half * 2 + 1] + sc * lora1 + b2[n + 1];
                *(float2*)(out + (size_t)m * Dd + n) = o;
            }
        }
    }
}

// ---------------------------------------------------------------------------
extern "C" void kernel_launch(void* const* d_in, const int* in_sizes, int n_in,
                              void* d_out, int out_size) {
    const float* x     = (const float*)d_in[0];
    const float* W1    = (const float*)d_in[1];
    const float* b1    = (const float*)d_in[2];
    const float* W2    = (const float*)d_in[3];
    const float* b2    = (const float*)d_in[4];
    const float* scale = (const float*)d_in[5];
    float* out = (float*)d_out;

    cudaFuncSetAttribute(gemm1_mma, cudaFuncAttributeMaxDynamicSharedMemorySize, SMEM_TOTAL);
    cudaFuncSetAttribute(gemm2_mma, cudaFuncAttributeMaxDynamicSharedMemorySize, SMEM_TOTAL);

    __half *xh, *w1h, *w2h;
    cudaGetSymbolAddress((void**)&xh, g_xh);
    cudaGetSymbolAddress((void**)&w1h, g_w1h);
    cudaGetSymbolAddress((void**)&w2h, g_w2h);

    u1_kernel<<<MM / 8, 256>>>(x);

    cvt_all_kernel<<<(N4_HALF + 255) / 256, 256>>>(x, W1, W2, xh, w1h, w2h);

    dim3 g1(Hh / 128, MM / 128);   // (32, 64)
    gemm1_mma<<<g1, 256, SMEM_TOTAL>>>(x, b1, scale);

    v_kernel<<<MM / 8, 256>>>(x);

    dim3 g2(Dd / 128, MM / 128);   // (8, 64)
    gemm2_mma<<<g2, 256, SMEM_TOTAL>>>(x, b2, scale, out);
}

// round 17
// speedup vs baseline: 1.3222x; 1.0199x over previous
#include <cuda_runtime.h>
#include <cuda_fp16.h>
#include <math.h>
#include <stdint.h>

// Problem constants
#define Bb 4
#define Ss 2048
#define Dd 1024
#define Hh 4096
#define MM (Bb * Ss)   // 8192

// ---------------------------------------------------------------------------
// Device-global scratch (allocation-free rule). fp16 (rn-rounded) operands.
// ---------------------------------------------------------------------------
__device__ __half g_xh[(size_t)MM * Dd];
__device__ __half g_w1h[(size_t)Hh * Dd];
__device__ __half g_w2h[(size_t)Dd * Hh];
__device__ __half g_hh[(size_t)MM * Hh];   // post-GELU hidden, fp16
__device__ float g_U1[MM * 4];
__device__ float g_V[MM * 16];

__device__ __forceinline__ float gelu_exact(float v) {
    return 0.5f * v * (1.0f + erff(v * 0.70710678118654752f));
}

__device__ __forceinline__ uint32_t smem_u32(const void* p) {
    uint32_t a;
    asm("{ .reg .u64 t; cvta.to.shared.u64 t, %1; cvt.u32.u64 %0, t; }"
        : "=r"(a) : "l"(p));
    return a;
}

// ---------------------------------------------------------------------------
// fp16 mma / ldmatrix / cp.async primitives
// ---------------------------------------------------------------------------
__device__ __forceinline__ void mma16816h(float* d, const uint32_t* a, const uint32_t* b) {
    asm volatile(
        "mma.sync.aligned.m16n8k16.row.col.f32.f16.f16.f32 "
        "{%0,%1,%2,%3}, {%4,%5,%6,%7}, {%8,%9}, {%0,%1,%2,%3};"
        : "+f"(d[0]), "+f"(d[1]), "+f"(d[2]), "+f"(d[3])
        : "r"(a[0]), "r"(a[1]), "r"(a[2]), "r"(a[3]), "r"(b[0]), "r"(b[1]));
}

__device__ __forceinline__ void ldm4(uint32_t* r, uint32_t addr) {
    asm volatile("ldmatrix.sync.aligned.m8n8.x4.shared.b16 {%0,%1,%2,%3}, [%4];"
                 : "=r"(r[0]), "=r"(r[1]), "=r"(r[2]), "=r"(r[3]) : "r"(addr));
}

__device__ __forceinline__ void cp16(uint32_t s, const void* g) {
    asm volatile("cp.async.cg.shared.global [%0], [%1], 16;" :: "r"(s), "l"(g));
}
__device__ __forceinline__ void cp_commit() {
    asm volatile("cp.async.commit_group;" ::: "memory");
}
template <int N>
__device__ __forceinline__ void cp_wait() {
    asm volatile("cp.async.wait_group %0;" :: "n"(N) : "memory");
}

// ---------------------------------------------------------------------------
// GEMM tiling (champion, unchanged): 128x128 tile, BK=64, 3-stage ring,
// one sync per chunk, interleaved cp.async issue, 2 CTAs/SM.
// ---------------------------------------------------------------------------
#define BK 64
#define TSTRIDE 144
#define TILE_B (128 * TSTRIDE)
#define STAGE_B (2 * TILE_B)
#define NSTAGE 3
#define SMEM_TOTAL (NSTAGE * STAGE_B) // 110592 B

extern __shared__ char dsmem[];

__device__ __forceinline__ void issue_chunk(
    uint32_t sbuf, const __half* __restrict__ Ah, const __half* __restrict__ Bh,
    int m0, int n0, int kc, int KDIM, int tid)
{
    #pragma unroll
    for (int i = 0; i < 4; i++) {
        int idx = tid + i * 256;
        int row = idx >> 3, c = idx & 7;
        uint32_t soff = (uint32_t)(row * TSTRIDE + c * 16);
        size_t ga = (size_t)(m0 + row) * KDIM + kc * BK + c * 8;
        size_t gb = (size_t)(n0 + row) * KDIM + kc * BK + c * 8;
        cp16(sbuf + soff, Ah + ga);
        cp16(sbuf + TILE_B + soff, Bh + gb);
    }
}

__device__ __forceinline__ void lda(uint32_t a[4][4], uint32_t tile, int wm, int lane, int ks) {
    uint32_t koff = (uint32_t)(ks * 32 + (lane >> 4) * 16);
    #pragma unroll
    for (int mi = 0; mi < 4; mi++) {
        uint32_t addr = tile + (uint32_t)((wm * 64 + mi * 16 + (lane & 15)) * TSTRIDE) + koff;
        ldm4(a[mi], addr);
    }
}

__device__ __forceinline__ void ldb(uint32_t b[4][2], uint32_t tile, int wn, int lane, int ks) {
    #pragma unroll
    for (int g = 0; g < 2; g++) {
        int nrow = wn * 32 + g * 16 + (lane & 7) + ((lane >> 4) & 1) * 8;
        uint32_t addr = tile + (uint32_t)(nrow * TSTRIDE) +
                        (uint32_t)(ks * 32 + ((lane >> 3) & 1) * 16);
        uint32_t r[4];
        ldm4(r, addr);
        b[2 * g][0] = r[0]; b[2 * g][1] = r[1];
        b[2 * g + 1][0] = r[2]; b[2 * g + 1][1] = r[3];
    }
}

__device__ __forceinline__ void compute_chunk_fused(
    uint32_t sbuf, int wm, int wn, int lane, float acc[4][4][4],
    bool do_issue, uint32_t sbuf_n,
    const __half* __restrict__ Ah, const __half* __restrict__ Bh,
    int m0, int n0, int kc, int KDIM, int tid)
{
    #pragma unroll
    for (int ks = 0; ks < 4; ks++) {
        if (do_issue) {
            int idx = tid + ks * 256;
            int row = idx >> 3, c = idx & 7;
            uint32_t soff = (uint32_t)(row * TSTRIDE + c * 16);
            size_t ga = (size_t)(m0 + row) * KDIM + kc * BK + c * 8;
            size_t gb = (size_t)(n0 + row) * KDIM + kc * BK + c * 8;
            cp16(sbuf_n + soff, Ah + ga);
            cp16(sbuf_n + TILE_B + soff, Bh + gb);
        }
        uint32_t a[4][4], b[4][2];
        lda(a, sbuf, wm, lane, ks);
        ldb(b, sbuf + TILE_B, wn, lane, ks);
        #pragma unroll
        for (int mi = 0; mi < 4; mi++)
            #pragma unroll
            for (int ni = 0; ni < 4; ni++)
                mma16816h(acc[mi][ni], a[mi], b[ni]);
    }
}

template <int KDIM>
__device__ __forceinline__ void gemm_f16(
    const __half* __restrict__ Ah, const __half* __restrict__ Bh,
    int m0, int n0, float acc[4][4][4])
{
    int tid = threadIdx.x;
    int lane = tid & 31, wid = tid >> 5;
    int wm = wid >> 2, wn = wid & 3;
    uint32_t sbase = smem_u32(dsmem);

    #pragma unroll
    for (int mi = 0; mi < 4; mi++)
        #pragma unroll
        for (int ni = 0; ni < 4; ni++)
            #pragma unroll
            for (int q = 0; q < 4; q++) acc[mi][ni][q] = 0.f;

    const int NC = KDIM / BK;
    issue_chunk(sbase + 0 * STAGE_B, Ah, Bh, m0, n0, 0, KDIM, tid);
    cp_commit();
    issue_chunk(sbase + 1 * STAGE_B, Ah, Bh, m0, n0, 1, KDIM, tid);
    cp_commit();

    int st_c = 0;
    for (int c = 0; c < NC; c++) {
        if (c + 1 < NC) cp_wait<1>();
        else            cp_wait<0>();
        __syncthreads();
        bool di = (c + 2 < NC);
        int st_n = st_c + 2; if (st_n >= NSTAGE) st_n -= NSTAGE;
        compute_chunk_fused(sbase + st_c * STAGE_B, wm, wn, lane, acc,
                            di, sbase + st_n * STAGE_B,
                            Ah, Bh, m0, n0, c + 2, KDIM, tid);
        if (di) cp_commit();
        if (++st_c == NSTAGE) st_c = 0;
    }
}

// ---------------------------------------------------------------------------
// Prologue kernel: blocks [0, MM/8) do U1; blocks beyond do cvt (MLP 4).
// ---------------------------------------------------------------------------
#define N4_X  (MM * Dd / 4)   // 2097152
#define N4_W1 (Hh * Dd / 4)   // 1048576
#define N4_W2 (Dd * Hh / 4)   // 1048576
#define N4_HALF (N4_X)        // x half == W1+W2 half
#define U1_BLOCKS (MM / 8)    // 1024
#define CVT_PAIRS (N4_HALF / 2)            // threads needed: each does 2x + 2w
#define CVT_BLOCKS ((CVT_PAIRS + 255) / 256)
#define PRO_BLOCKS (U1_BLOCKS + CVT_BLOCKS)

__global__ void prologue_kernel(const float* __restrict__ x,
                                const float* __restrict__ W1,
                                const float* __restrict__ W2,
                                __half* __restrict__ xh,
                                __half* __restrict__ w1h,
                                __half* __restrict__ w2h) {
    if (blockIdx.x < U1_BLOCKS) {
        // ---- U1[b,s,r] = x[b,s,:] . x[b, 2+2r, :]; 1 warp per (b,s) ----
        int gw = (blockIdx.x * blockDim.x + threadIdx.x) >> 5;
        int lane = threadIdx.x & 31;
        int b = gw >> 11;
        const float4* xr = (const float4*)(x + (size_t)gw * Dd);
        const float4* od[4];
        #pragma unroll
        for (int r = 0; r < 4; r++)
            od[r] = (const float4*)(x + ((size_t)b * Ss + 2 + 2 * r) * Dd);
        float a[4] = {0.f, 0.f, 0.f, 0.f};
        #pragma unroll
        for (int t0 = 0; t0 < 2; t0++) {
            float4 xv[4];
            #pragma unroll
            for (int t = 0; t < 4; t++)
                xv[t] = xr[lane + (t0 * 4 + t) * 32];
            #pragma unroll
            for (int t = 0; t < 4; t++) {
                int j = lane + (t0 * 4 + t) * 32;
                #pragma unroll
                for (int r = 0; r < 4; r++) {
                    float4 v = od[r][j];
                    a[r] += xv[t].x * v.x + xv[t].y * v.y + xv[t].z * v.z + xv[t].w * v.w;
                }
            }
        }
        #pragma unroll
        for (int r = 0; r < 4; r++) {
            #pragma unroll
            for (int off = 16; off; off >>= 1)
                a[r] += __shfl_xor_sync(0xFFFFFFFFu, a[r], off);
        }
        if (lane == 0) {
            #pragma unroll
            for (int r = 0; r < 4; r++) g_U1[gw * 4 + r] = a[r];
        }
    } else {
        // ---- cvt fp32->fp16, 4 independent float4 loads per thread ----
        int i = (blockIdx.x - U1_BLOCKS) * blockDim.x + threadIdx.x;
        if (i >= CVT_PAIRS) return;
        int ix = 2 * i;                     // two x float4s: ix, ix+1
        float4 vx0 = ((const float4*)x)[ix];
        float4 vx1 = ((const float4*)x)[ix + 1];
        const float* src1; __half* dst1; int j1;
        if (ix < N4_W1) { src1 = W1; dst1 = w1h; j1 = ix; }
        else            { src1 = W2; dst1 = w2h; j1 = ix - N4_W1; }
        float4 vw0 = ((const float4*)src1)[j1];
        float4 vw1 = ((const float4*)src1)[j1 + 1];

        __half2* dx = (__half2*)xh;
        dx[2 * ix]     = __floats2half2_rn(vx0.x, vx0.y);
        dx[2 * ix + 1] = __floats2half2_rn(vx0.z, vx0.w);
        dx[2 * ix + 2] = __floats2half2_rn(vx1.x, vx1.y);
        dx[2 * ix + 3] = __floats2half2_rn(vx1.z, vx1.w);
        __half2* d1 = (__half2*)dst1;
        d1[2 * j1]     = __floats2half2_rn(vw0.x, vw0.y);
        d1[2 * j1 + 1] = __floats2half2_rn(vw0.z, vw0.w);
        d1[2 * j1 + 2] = __floats2half2_rn(vw1.x, vw1.y);
        d1[2 * j1 + 3] = __floats2half2_rn(vw1.z, vw1.w);
    }
}

// ---------------------------------------------------------------------------
// V[b,s,r,k] = sum_j h[b,s,k*1024+j] * x[b,10+2r,j]; h streamed as uint4,
// 8 loads batched per outer step (MLP 8).
// ---------------------------------------------------------------------------
__global__ void v_kernel(const float* __restrict__ x) {
    int gw = (blockIdx.x * blockDim.x + threadIdx.x) >> 5;
    int lane = threadIdx.x & 31;
    if (gw >= MM) return;
    int b = gw >> 11;
    const float4* od[4];
    #pragma unroll
    for (int r = 0; r < 4; r++)
        od[r] = (const float4*)(x + ((size_t)b * Ss + 10 + 2 * r) * Dd);
    float acc[16];
    #pragma unroll
    for (int i = 0; i < 16; i++) acc[i] = 0.f;

    const uint4* hr = (const uint4*)(g_hh + (size_t)gw * Hh);   // 512 uint4
    #pragma unroll
    for (int t2 = 0; t2 < 2; t2++) {          // two k-block pairs
        uint4 hv[8];
        #pragma unroll
        for (int t = 0; t < 8; t++)
            hv[t] = hr[t2 * 256 + lane + t * 32];   // 8 batched 16B loads
        #pragma unroll
        for (int t = 0; t < 8; t++) {
            int k = t2 * 2 + (t >> 2);        // k-block of this load
            int j8 = lane + (t & 3) * 32;     // 8-half group within k-block
            float2 f0 = __half22float2(*(const __half2*)&hv[t].x);
            float2 f1 = __half22float2(*(const __half2*)&hv[t].y);
            float2 f2 = __half22float2(*(const __half2*)&hv[t].z);
            float2 f3 = __half22float2(*(const __half2*)&hv[t].w);
            #pragma unroll
            for (int r = 0; r < 4; r++) {
                float4 x0 = od[r][2 * j8];
                float4 x1 = od[r][2 * j8 + 1];
                acc[r * 4 + k] += f0.x * x0.x + f0.y * x0.y + f1.x * x0.z + f1.y * x0.w
                                + f2.x * x1.x + f2.y * x1.y + f3.x * x1.z + f3.y * x1.w;
            }
        }
    }
    #pragma unroll
    for (int i = 0; i < 16; i++) {
        #pragma unroll
        for (int off = 16; off; off >>= 1)
            acc[i] += __shfl_xor_sync(0xFFFFFFFFu, acc[i], off);
    }
    if (lane == 0) {
        #pragma unroll
        for (int i = 0; i < 16; i++) g_V[gw * 16 + i] = acc[i];
    }
}

// ---------------------------------------------------------------------------
// GEMM1: h = gelu(x@W1^T + scale*lora1 + b1) -> fp16 g_hh
// ---------------------------------------------------------------------------
__global__ __launch_bounds__(256, 2)
void gemm1_mma(const float* __restrict__ x, const float* __restrict__ b1,
               const float* __restrict__ scale_p) {
    int m0 = blockIdx.y * 128, n0 = blockIdx.x * 128;
    float acc[4][4][4];
    gemm_f16<Dd>(g_xh, g_w1h, m0, n0, acc);

    int lane = threadIdx.x & 31, wid = threadIdx.x >> 5;
    int wm = wid >> 2, wn = wid & 3;
    float sc = *scale_p;
    int r = n0 >> 10;
    #pragma unroll
    for (int mi = 0; mi < 4; mi++) {
        #pragma unroll
        for (int half = 0; half < 2; half++) {
            int m = m0 + wm * 64 + mi * 16 + (lane >> 2) + half * 8;
            int b = m >> 11;
            float u = sc * g_U1[m * 4 + r];
            const float* ev = x + ((size_t)b * Ss + 1 + 2 * r) * Dd;
            #pragma unroll
            for (int ni = 0; ni < 4; ni++) {
                int n = n0 + wn * 32 + ni * 8 + 2 * (lane & 3);
                int nc = n & 1023;
                float c0 = acc[mi][ni][half * 2 + 0] + u * ev[nc]     + b1[n];
                float c1 = acc[mi][ni][half * 2 + 1] + u * ev[nc + 1] + b1[n + 1];
                *(__half2*)(g_hh + (size_t)m * Hh + n) =
                    __floats2half2_rn(gelu_exact(c0), gelu_exact(c1));
            }
        }
    }
}

// ---------------------------------------------------------------------------
// GEMM2: out = h@W2^T + scale*lora2 + b2  (fp32 out)
// ---------------------------------------------------------------------------
__global__ __launch_bounds__(256, 2)
void gemm2_mma(const float* __restrict__ x, const float* __restrict__ b2,
               const float* __restrict__ scale_p, float* __restrict__ out) {
    int m0 = blockIdx.y * 128, n0 = blockIdx.x * 128;
    float acc[4][4][4];
    gemm_f16<Hh>(g_hh, g_w2h, m0, n0, acc);

    int lane = threadIdx.x & 31, wid = threadIdx.x >> 5;
    int wm = wid >> 2, wn = wid & 3;
    float sc = *scale_p;
    int r = n0 >> 8;
    #pragma unroll
    for (int mi = 0; mi < 4; mi++) {
        #pragma unroll
        for (int half = 0; half < 2; half++) {
            int m = m0 + wm * 64 + mi * 16 + (lane >> 2) + half * 8;
            int b = m >> 11;
            float4 vv = *(const float4*)&g_V[m * 16 + r * 4];
            const float4* ev2 = (const float4*)(x + ((size_t)b * Ss + 9 + 2 * r) * Dd);
            #pragma unroll
            for (int ni = 0; ni < 4; ni++) {
                int n = n0 + wn * 32 + ni * 8 + 2 * (lane & 3);
                float4 e0 = ev2[n & 255];
                float4 e1 = ev2[(n + 1) & 255];
                float lora0 = vv.x * e0.x + vv.y * e0.y + vv.z * e0.z + vv.w * e0.w;
                float lora1 = vv.x * e1.x + vv.y * e1.y + vv.z * e1.z + vv.w * e1.w;
                float2 o;
                o.x = acc[mi][ni][half * 2 + 0] + sc * lora0 + b2[n];
                o.y = acc[mi][ni][half * 2 + 1] + sc * lora1 + b2[n + 1];
                *(float2*)(out + (size_t)m * Dd + n) = o;
            }
        }
    }
}

// ---------------------------------------------------------------------------
extern "C" void kernel_launch(void* const* d_in, const int* in_sizes, int n_in,
                              void* d_out, int out_size) {
    const float* x     = (const float*)d_in[0];
    const float* W1    = (const float*)d_in[1];
    const float* b1    = (const float*)d_in[2];
    const float* W2    = (const float*)d_in[3];
    const float* b2    = (const float*)d_in[4];
    const float* scale = (const float*)d_in[5];
    float* out = (float*)d_out;

    cudaFuncSetAttribute(gemm1_mma, cudaFuncAttributeMaxDynamicSharedMemorySize, SMEM_TOTAL);
    cudaFuncSetAttribute(gemm2_mma, cudaFuncAttributeMaxDynamicSharedMemorySize, SMEM_TOTAL);

    __half *xh, *w1h, *w2h;
    cudaGetSymbolAddress((void**)&xh, g_xh);
    cudaGetSymbolAddress((void**)&w1h, g_w1h);
    cudaGetSymbolAddress((void**)&w2h, g_w2h);

    prologue_kernel<<<PRO_BLOCKS, 256>>>(x, W1, W2, xh, w1h, w2h);

    dim3 g1(Hh / 128, MM / 128);   // (32, 64)
    gemm1_mma<<<g1, 256, SMEM_TOTAL>>>(x, b1, scale);

    v_kernel<<<MM / 8, 256>>>(x);

    dim3 g2(Dd / 128, MM / 128);   // (8, 64)
    gemm2_mma<<<g2, 256, SMEM_TOTAL>>>(x, b2, scale, out);
}